// round 10
// baseline (speedup 1.0000x reference)
#include <cuda_runtime.h>
#include <math_constants.h>
#include <cstdint>

// KNN_18614388261211 — farthest-(k+1) selection, drop rank 0.
// x: (8,2048,3) f32 -> BN=16384 points, k=16.
// out: [ dists (BN*16 f32 = pair values) | idx (BN*16 as f32) ]
//
// R9 vs R8 (234us): slow-path latency attack.
//   - row-interleaved insertion: one lockstep loop extracts one source per row
//     per step -> 4 independent shuffle/vote chains in flight (was serial)
//   - branch-free insert body (selects, no BSSY/BSYNC per source)
//   - hot loop + exact comparator unchanged (bit-identical results)

#define BN       16384
#define KOUT     16
#define R        4                 // rows per warp
#define NW       32                // warps per block
#define NTHREADS (NW * 32)         // 1024
#define NBLOCKS  (BN / (NW * R))   // 128
#define NITER2   (BN / 64)         // 256 iterations, 64 candidates each
#define SMEM_BYTES (BN * 3 * 4)    // 192 KB: float2 xy[BN] + float z[BN]
#define SLACK    1e-3f             // conservative filter slack (>> max fma-vs-rn error)

__device__ __forceinline__ float fneg(float v) {
    return __int_as_float(__float_as_int(v) ^ 0x80000000u);
}

// Slow path for one candidate. BARR[r] = ballot of lanes whose candidate
// qualified for row r (warp-uniform). Rows drained in LOCKSTEP so their
// shuffle/vote chains interleave. Branch-free updates.
#define PROCESS_CAND(QX, QY, QZ, BARR, NJBASE)                                  \
    do {                                                                        \
        const float nsqj_ = fneg(__fadd_rn(__fadd_rn(__fmul_rn((QX), (QX)),     \
                                                     __fmul_rn((QY), (QY))),    \
                                           __fmul_rn((QZ), (QZ))));             \
        float pv_[R];                                                           \
        _Pragma("unroll")                                                       \
        for (int r_ = 0; r_ < R; r_++) {                                        \
            const float dot2x_ = __fadd_rn(__fadd_rn(__fmul_rn(px2[r_], (QX)),  \
                                                     __fmul_rn(py2[r_], (QY))), \
                                           __fmul_rn(pz2[r_], (QZ)));           \
            pv_[r_] = __fadd_rn(__fadd_rn(dot2x_, nsqi[r_]), nsqj_);            \
        }                                                                       \
        while ((BARR[0] | BARR[1] | BARR[2] | BARR[3]) != 0u) {                 \
            _Pragma("unroll")                                                   \
            for (int r_ = 0; r_ < R; r_++) {                                    \
                const bool valid_ = (BARR[r_] != 0u);   /* warp-uniform */      \
                const int  src_ = (__ffs(BARR[r_]) - 1) & 31;                   \
                BARR[r_] &= BARR[r_] - 1u;                                      \
                const float nv_ = __shfl_sync(FULL, pv_[r_], src_);             \
                const int   nj_ = (NJBASE) + 2 * src_;                          \
                const bool after_ = valid_ && (lane <= 16) &&                   \
                    ((lv[r_] > nv_) || (lv[r_] == nv_ && lj[r_] > nj_));        \
                const unsigned im_ = __ballot_sync(FULL, after_) & 0x1ffffu;    \
                const float upv_ = __shfl_up_sync(FULL, lv[r_], 1);             \
                const int   upj_ = __shfl_up_sync(FULL, lj[r_], 1);             \
                const int pos_ = __ffs(im_) - 1;        /* -1 if im_==0 */      \
                const bool shift_ = (im_ != 0u) && (lane <= 16) && (lane > pos_); \
                const bool take_  = (lane == pos_);     /* pos_==-1: never */   \
                lv[r_] = take_ ? nv_ : (shift_ ? upv_ : lv[r_]);                \
                lj[r_] = take_ ? nj_ : (shift_ ? upj_ : lj[r_]);                \
            }                                                                   \
        }                                                                       \
        _Pragma("unroll")                                                       \
        for (int r_ = 0; r_ < R; r_++) {                                        \
            const float nt_ = __shfl_sync(FULL, lv[r_], 16);                    \
            cR[r_] = __fsub_rn(__fadd_rn(nsqi[r_], fneg(nt_)), SLACK);          \
        }                                                                       \
    } while (0)

__global__ __launch_bounds__(NTHREADS, 1)
void knn_kernel(const float* __restrict__ x, float* __restrict__ out) {
    extern __shared__ float smem[];
    float2* __restrict__ sxy = reinterpret_cast<float2*>(smem);  // [BN]
    float*  __restrict__ sz  = smem + 2 * BN;                    // [BN]

    for (int p = threadIdx.x; p < BN; p += NTHREADS) {
        sxy[p] = make_float2(x[3 * p + 0], x[3 * p + 1]);
        sz[p]  = x[3 * p + 2];
    }
    __syncthreads();

    const int lane = threadIdx.x & 31;
    const int warp = threadIdx.x >> 5;
    const int row0 = (blockIdx.x * NW + warp) * R;
    const unsigned FULL = 0xffffffffu;

    // Per-row scalar state — all compile-time indexed (no LMEM).
    float px2[R], py2[R], pz2[R], nsqi[R], cR[R], lv[R];
    int   lj[R];

#pragma unroll
    for (int r = 0; r < R; r++) {
        const float2 pxy = sxy[row0 + r];
        const float  pz  = sz[row0 + r];
        const float sqi = __fadd_rn(__fadd_rn(__fmul_rn(pxy.x, pxy.x),
                                              __fmul_rn(pxy.y, pxy.y)),
                                    __fmul_rn(pz, pz));
        px2[r] = __fadd_rn(pxy.x, pxy.x);   // exact doubling
        py2[r] = __fadd_rn(pxy.y, pxy.y);
        pz2[r] = __fadd_rn(pz, pz);
        nsqi[r] = fneg(sqi);
        cR[r]   = -CUDART_INF_F;            // T = +INF: admit everything
        lv[r] = CUDART_INF_F;               // lane l (0..16) holds rank-l
        lj[r] = 0x7fffffff;
    }

    for (int t = 0; t < NITER2; t++) {
        const int j0 = (t << 6) + (lane << 1);       // candidates j0, j0+1
        const float4 xy = *reinterpret_cast<const float4*>(sxy + j0); // LDS.128
        const float2 zz = *reinterpret_cast<const float2*>(sz + j0);  // LDS.64

        // Fast (fma-contracted) sqj per candidate (filter only).
        const float sqA = __fmaf_rn(xy.x, xy.x,
                          __fmaf_rn(xy.y, xy.y, __fmul_rn(zz.x, zz.x)));
        const float sqB = __fmaf_rn(xy.z, xy.z,
                          __fmaf_rn(xy.w, xy.w, __fmul_rn(zz.y, zz.y)));

        // m[r] = 2*dot_r + (-sqi_r - T_r - SLACK), per candidate.
        float mA[R], mB[R];
        float mnA = CUDART_INF_F, mnB = CUDART_INF_F;
#pragma unroll
        for (int r = 0; r < R; r++) {
            mA[r] = __fmaf_rn(pz2[r], zz.x,
                    __fmaf_rn(py2[r], xy.y,
                    __fmaf_rn(px2[r], xy.x, cR[r])));
            mB[r] = __fmaf_rn(pz2[r], zz.y,
                    __fmaf_rn(py2[r], xy.w,
                    __fmaf_rn(px2[r], xy.z, cR[r])));
            mnA = fminf(mnA, mA[r]);
            mnB = fminf(mnB, mB[r]);
        }

        const bool qA = mnA < sqA;
        const bool qB = mnB < sqB;
        if (__any_sync(FULL, qA || qB)) {
            unsigned bA[R], bB[R];
#pragma unroll
            for (int r = 0; r < R; r++) {
                bA[r] = __ballot_sync(FULL, mA[r] < sqA);
                bB[r] = __ballot_sync(FULL, mB[r] < sqB);
            }
            const int njbase = t << 6;
            if ((bA[0] | bA[1] | bA[2] | bA[3]) != 0u)
                PROCESS_CAND(xy.x, xy.y, zz.x, bA, njbase);
            if ((bB[0] | bB[1] | bB[2] | bB[3]) != 0u)
                PROCESS_CAND(xy.z, xy.w, zz.y, bB, njbase + 1);
        }
    }

    // Ranks 1..16 are the output (rank 0 dropped by the reference).
#pragma unroll
    for (int r = 0; r < R; r++) {
        if (lane >= 1 && lane <= 16) {
            const int row = row0 + r;
            out[(size_t)row * KOUT + (lane - 1)] = lv[r];
            out[(size_t)BN * KOUT + (size_t)row * KOUT + (lane - 1)] = (float)lj[r];
        }
    }
}

extern "C" void kernel_launch(void* const* d_in, const int* in_sizes, int n_in,
                              void* d_out, int out_size) {
    const float* x = (const float*)d_in[0];
    float* out = (float*)d_out;
    cudaFuncSetAttribute(knn_kernel, cudaFuncAttributeMaxDynamicSharedMemorySize,
                         SMEM_BYTES);
    knn_kernel<<<NBLOCKS, NTHREADS, SMEM_BYTES>>>(x, out);
}

// round 12
// speedup vs baseline: 1.4948x; 1.4948x over previous
#include <cuda_runtime.h>
#include <math_constants.h>
#include <cstdint>

// KNN_18614388261211 — farthest-(k+1) selection, drop rank 0.
// x: (8,2048,3) f32 -> BN=16384 points, k=16.
// out: [ dists (BN*16 f32 = pair values) | idx (BN*16 as f32) ]
//
// R10 = R8 (best, 234us) + bitonic bootstrap:
//   - first 64 candidates per row sorted via 64-elem warp bitonic (2 regs/lane,
//     lexicographic (pv,idx) comparator) -> ranks 0..16 seed the list directly.
//     Replaces iteration-0's ~256 serial insert chains (~3.3K instr/warp).
//   - main loop starts at t=1; everything else identical to R8 (bit-identical).

#define BN       16384
#define KOUT     16
#define R        4                 // rows per warp
#define NW       32                // warps per block
#define NTHREADS (NW * 32)         // 1024
#define NBLOCKS  (BN / (NW * R))   // 128
#define NITER2   (BN / 64)         // 256 candidate groups of 64
#define SMEM_BYTES (BN * 3 * 4)    // 192 KB: float2 xy[BN] + float z[BN]
#define SLACK    1e-3f             // conservative filter slack (>> max fma-vs-rn error)

__device__ __forceinline__ float fneg(float v) {
    return __int_as_float(__float_as_int(v) ^ 0x80000000u);
}

// Slow path for one candidate (QX,QY,QZ) with hot-loop filter values MARR[].
// Macro so all arrays stay compile-time indexed -> registers. (Identical to R8.)
#define PROCESS_CAND(QX, QY, QZ, MARR, SQJF, NJBASE)                            \
    do {                                                                        \
        const float nsqj_ = fneg(__fadd_rn(__fadd_rn(__fmul_rn((QX), (QX)),     \
                                                     __fmul_rn((QY), (QY))),    \
                                           __fmul_rn((QZ), (QZ))));             \
        _Pragma("unroll")                                                       \
        for (int r_ = 0; r_ < R; r_++) {                                        \
            unsigned b_ = __ballot_sync(FULL, MARR[r_] < (SQJF));               \
            if (!b_) continue;                                                  \
            const float dot2x_ = __fadd_rn(__fadd_rn(__fmul_rn(px2[r_], (QX)),  \
                                                     __fmul_rn(py2[r_], (QY))), \
                                           __fmul_rn(pz2[r_], (QZ)));           \
            const float pv_ = __fadd_rn(__fadd_rn(dot2x_, nsqi[r_]), nsqj_);    \
            bool inserted_ = false;                                             \
            while (b_) {                                                        \
                const int src_ = __ffs(b_) - 1;                                 \
                b_ &= b_ - 1;                                                   \
                const float nv_ = __shfl_sync(FULL, pv_, src_);                 \
                const int   nj_ = (NJBASE) + 2 * src_;                          \
                const bool after_ = (lane <= 16) &&                             \
                    ((lv[r_] > nv_) || (lv[r_] == nv_ && lj[r_] > nj_));        \
                const unsigned im_ = __ballot_sync(FULL, after_) & 0x1ffffu;    \
                const float upv_ = __shfl_up_sync(FULL, lv[r_], 1);             \
                const int   upj_ = __shfl_up_sync(FULL, lj[r_], 1);             \
                if (im_) {                                                      \
                    const int pos_ = __ffs(im_) - 1;                            \
                    if (lane <= 16) {                                           \
                        if (lane > pos_)       { lv[r_] = upv_; lj[r_] = upj_; }\
                        else if (lane == pos_) { lv[r_] = nv_;  lj[r_] = nj_;  }\
                    }                                                           \
                    inserted_ = true;                                           \
                }                                                               \
            }                                                                   \
            if (inserted_) {                                                    \
                const float nt_ = __shfl_sync(FULL, lv[r_], 16);                \
                cR[r_] = __fsub_rn(__fadd_rn(nsqi[r_], fneg(nt_)), SLACK);      \
            }                                                                   \
        }                                                                       \
    } while (0)

__global__ __launch_bounds__(NTHREADS, 1)
void knn_kernel(const float* __restrict__ x, float* __restrict__ out) {
    extern __shared__ float smem[];
    float2* __restrict__ sxy = reinterpret_cast<float2*>(smem);  // [BN]
    float*  __restrict__ sz  = smem + 2 * BN;                    // [BN]

    for (int p = threadIdx.x; p < BN; p += NTHREADS) {
        sxy[p] = make_float2(x[3 * p + 0], x[3 * p + 1]);
        sz[p]  = x[3 * p + 2];
    }
    __syncthreads();

    const int lane = threadIdx.x & 31;
    const int warp = threadIdx.x >> 5;
    const int row0 = (blockIdx.x * NW + warp) * R;
    const unsigned FULL = 0xffffffffu;

    // Per-row scalar state — all compile-time indexed (no LMEM).
    float px2[R], py2[R], pz2[R], nsqi[R], cR[R], lv[R];
    int   lj[R];

#pragma unroll
    for (int r = 0; r < R; r++) {
        const float2 pxy = sxy[row0 + r];
        const float  pz  = sz[row0 + r];
        const float sqi = __fadd_rn(__fadd_rn(__fmul_rn(pxy.x, pxy.x),
                                              __fmul_rn(pxy.y, pxy.y)),
                                    __fmul_rn(pz, pz));
        px2[r] = __fadd_rn(pxy.x, pxy.x);   // exact doubling
        py2[r] = __fadd_rn(pxy.y, pxy.y);
        pz2[r] = __fadd_rn(pz, pz);
        nsqi[r] = fneg(sqi);
    }

    // ---- Bootstrap: sort candidates 0..63 per row, seed list with ranks 0..16.
    {
        // Candidates 2*lane, 2*lane+1 (virtual index v = 2*lane + slot).
        const float4 xy = *reinterpret_cast<const float4*>(sxy + (lane << 1));
        const float2 zz = *reinterpret_cast<const float2*>(sz + (lane << 1));
        const float nsq0 = fneg(__fadd_rn(__fadd_rn(__fmul_rn(xy.x, xy.x),
                                                    __fmul_rn(xy.y, xy.y)),
                                          __fmul_rn(zz.x, zz.x)));
        const float nsq1 = fneg(__fadd_rn(__fadd_rn(__fmul_rn(xy.z, xy.z),
                                                    __fmul_rn(xy.w, xy.w)),
                                          __fmul_rn(zz.y, zz.y)));
#pragma unroll
        for (int r = 0; r < R; r++) {
            // Exact pv (same formula as slow path -> bit-identical to R8).
            const float d0 = __fadd_rn(__fadd_rn(__fmul_rn(px2[r], xy.x),
                                                 __fmul_rn(py2[r], xy.y)),
                                       __fmul_rn(pz2[r], zz.x));
            const float d1 = __fadd_rn(__fadd_rn(__fmul_rn(px2[r], xy.z),
                                                 __fmul_rn(py2[r], xy.w)),
                                       __fmul_rn(pz2[r], zz.y));
            float pv0 = __fadd_rn(__fadd_rn(d0, nsqi[r]), nsq0);
            float pv1 = __fadd_rn(__fadd_rn(d1, nsqi[r]), nsq1);
            int   id0 = (lane << 1);
            int   id1 = (lane << 1) + 1;

            // 64-element bitonic sort, ascending lexicographic (pv, id).
#pragma unroll
            for (int k = 2; k <= 64; k <<= 1) {
#pragma unroll
                for (int j = k >> 1; j >= 1; j >>= 1) {
                    const bool asc = (k == 64) || ((lane & (k >> 1)) == 0);
                    if (j >= 2) {
                        const int L = j >> 1;
                        const float opv0 = __shfl_xor_sync(FULL, pv0, L);
                        const float opv1 = __shfl_xor_sync(FULL, pv1, L);
                        const int   oid0 = __shfl_xor_sync(FULL, id0, L);
                        const int   oid1 = __shfl_xor_sync(FULL, id1, L);
                        const bool lower = (lane & L) == 0;
                        const bool keepmin = (asc == lower);
                        // ids distinct -> strict total order, no equal case
                        const bool l0 = (opv0 < pv0) || (opv0 == pv0 && oid0 < id0);
                        const bool l1 = (opv1 < pv1) || (opv1 == pv1 && oid1 < id1);
                        if (keepmin ? l0 : !l0) { pv0 = opv0; id0 = oid0; }
                        if (keepmin ? l1 : !l1) { pv1 = opv1; id1 = oid1; }
                    } else {
                        // local compare-exchange slot0 <-> slot1
                        const bool less = (pv1 < pv0) || (pv1 == pv0 && id1 < id0);
                        if (asc ? less : !less) {
                            const float tp = pv0; pv0 = pv1; pv1 = tp;
                            const int   ti = id0; id0 = id1; id1 = ti;
                        }
                    }
                }
            }
            // rank v = 2*lane + slot; redistribute so lane l holds rank l (l<=16)
            const float a0 = __shfl_sync(FULL, pv0, lane >> 1);
            const float a1 = __shfl_sync(FULL, pv1, lane >> 1);
            const int   b0 = __shfl_sync(FULL, id0, lane >> 1);
            const int   b1 = __shfl_sync(FULL, id1, lane >> 1);
            lv[r] = (lane <= 16) ? ((lane & 1) ? a1 : a0) : CUDART_INF_F;
            lj[r] = (lane <= 16) ? ((lane & 1) ? b1 : b0) : 0x7fffffff;
            const float nt = __shfl_sync(FULL, lv[r], 16);
            cR[r] = __fsub_rn(__fadd_rn(nsqi[r], fneg(nt)), SLACK);
        }
    }

    // ---- Main loop over candidate groups 1..255 (candidates 64..16383).
    for (int t = 1; t < NITER2; t++) {
        const int j0 = (t << 6) + (lane << 1);       // candidates j0, j0+1
        const float4 xy = *reinterpret_cast<const float4*>(sxy + j0); // LDS.128
        const float2 zz = *reinterpret_cast<const float2*>(sz + j0);  // LDS.64

        // Fast (fma-contracted) sqj per candidate (filter only).
        const float sqA = __fmaf_rn(xy.x, xy.x,
                          __fmaf_rn(xy.y, xy.y, __fmul_rn(zz.x, zz.x)));
        const float sqB = __fmaf_rn(xy.z, xy.z,
                          __fmaf_rn(xy.w, xy.w, __fmul_rn(zz.y, zz.y)));

        // m[r] = 2*dot_r + (-sqi_r - T_r - SLACK), per candidate.
        float mA[R], mB[R];
        float mnA = CUDART_INF_F, mnB = CUDART_INF_F;
#pragma unroll
        for (int r = 0; r < R; r++) {
            mA[r] = __fmaf_rn(pz2[r], zz.x,
                    __fmaf_rn(py2[r], xy.y,
                    __fmaf_rn(px2[r], xy.x, cR[r])));
            mB[r] = __fmaf_rn(pz2[r], zz.y,
                    __fmaf_rn(py2[r], xy.w,
                    __fmaf_rn(px2[r], xy.z, cR[r])));
            mnA = fminf(mnA, mA[r]);
            mnB = fminf(mnB, mB[r]);
        }

        const bool qA = mnA < sqA;
        const bool qB = mnB < sqB;
        if (__any_sync(FULL, qA || qB)) {
            const unsigned gA = __ballot_sync(FULL, qA);
            const unsigned gB = __ballot_sync(FULL, qB);
            const int njbase = t << 6;
            if (gA) PROCESS_CAND(xy.x, xy.y, zz.x, mA, sqA, njbase);
            if (gB) PROCESS_CAND(xy.z, xy.w, zz.y, mB, sqB, njbase + 1);
        }
    }

    // Ranks 1..16 are the output (rank 0 dropped by the reference).
#pragma unroll
    for (int r = 0; r < R; r++) {
        if (lane >= 1 && lane <= 16) {
            const int row = row0 + r;
            out[(size_t)row * KOUT + (lane - 1)] = lv[r];
            out[(size_t)BN * KOUT + (size_t)row * KOUT + (lane - 1)] = (float)lj[r];
        }
    }
}

extern "C" void kernel_launch(void* const* d_in, const int* in_sizes, int n_in,
                              void* d_out, int out_size) {
    const float* x = (const float*)d_in[0];
    float* out = (float*)d_out;
    cudaFuncSetAttribute(knn_kernel, cudaFuncAttributeMaxDynamicSharedMemorySize,
                         SMEM_BYTES);
    knn_kernel<<<NBLOCKS, NTHREADS, SMEM_BYTES>>>(x, out);
}

// round 13
// speedup vs baseline: 1.4965x; 1.0011x over previous
#include <cuda_runtime.h>
#include <math_constants.h>
#include <cstdint>

// KNN_18614388261211 — farthest-(k+1) selection, drop rank 0.
// x: (8,2048,3) f32 -> BN=16384 points, k=16.
// out: [ dists (BN*16 f32 = pair values) | idx (BN*16 as f32) ]
//
// R12 = R10 (best, 201us) + full-chip load balance:
//   grid 128 -> 152 (all SMs). Work indexed by global warp id over 4096
//   warp-tasks (4 rows each); ~27 busy warps/block instead of 32.
//   Selection logic untouched -> bit-identical output.

#define BN       16384
#define KOUT     16
#define R        4                 // rows per warp-task
#define NW       32                // warps per block
#define NTHREADS (NW * 32)         // 1024
#define NBLOCKS  152               // all SMs (was 128)
#define NTASKS   (BN / R)          // 4096 warp-tasks
#define NITER2   (BN / 64)         // 256 candidate groups of 64
#define SMEM_BYTES (BN * 3 * 4)    // 192 KB: float2 xy[BN] + float z[BN]
#define SLACK    1e-3f             // conservative filter slack (>> max fma-vs-rn error)

__device__ __forceinline__ float fneg(float v) {
    return __int_as_float(__float_as_int(v) ^ 0x80000000u);
}

// Slow path for one candidate (QX,QY,QZ) with hot-loop filter values MARR[].
// Macro so all arrays stay compile-time indexed -> registers.
#define PROCESS_CAND(QX, QY, QZ, MARR, SQJF, NJBASE)                            \
    do {                                                                        \
        const float nsqj_ = fneg(__fadd_rn(__fadd_rn(__fmul_rn((QX), (QX)),     \
                                                     __fmul_rn((QY), (QY))),    \
                                           __fmul_rn((QZ), (QZ))));             \
        _Pragma("unroll")                                                       \
        for (int r_ = 0; r_ < R; r_++) {                                        \
            unsigned b_ = __ballot_sync(FULL, MARR[r_] < (SQJF));               \
            if (!b_) continue;                                                  \
            const float dot2x_ = __fadd_rn(__fadd_rn(__fmul_rn(px2[r_], (QX)),  \
                                                     __fmul_rn(py2[r_], (QY))), \
                                           __fmul_rn(pz2[r_], (QZ)));           \
            const float pv_ = __fadd_rn(__fadd_rn(dot2x_, nsqi[r_]), nsqj_);    \
            bool inserted_ = false;                                             \
            while (b_) {                                                        \
                const int src_ = __ffs(b_) - 1;                                 \
                b_ &= b_ - 1;                                                   \
                const float nv_ = __shfl_sync(FULL, pv_, src_);                 \
                const int   nj_ = (NJBASE) + 2 * src_;                          \
                const bool after_ = (lane <= 16) &&                             \
                    ((lv[r_] > nv_) || (lv[r_] == nv_ && lj[r_] > nj_));        \
                const unsigned im_ = __ballot_sync(FULL, after_) & 0x1ffffu;    \
                const float upv_ = __shfl_up_sync(FULL, lv[r_], 1);             \
                const int   upj_ = __shfl_up_sync(FULL, lj[r_], 1);             \
                if (im_) {                                                      \
                    const int pos_ = __ffs(im_) - 1;                            \
                    if (lane <= 16) {                                           \
                        if (lane > pos_)       { lv[r_] = upv_; lj[r_] = upj_; }\
                        else if (lane == pos_) { lv[r_] = nv_;  lj[r_] = nj_;  }\
                    }                                                           \
                    inserted_ = true;                                           \
                }                                                               \
            }                                                                   \
            if (inserted_) {                                                    \
                const float nt_ = __shfl_sync(FULL, lv[r_], 16);                \
                cR[r_] = __fsub_rn(__fadd_rn(nsqi[r_], fneg(nt_)), SLACK);      \
            }                                                                   \
        }                                                                       \
    } while (0)

__global__ __launch_bounds__(NTHREADS, 1)
void knn_kernel(const float* __restrict__ x, float* __restrict__ out) {
    extern __shared__ float smem[];
    float2* __restrict__ sxy = reinterpret_cast<float2*>(smem);  // [BN]
    float*  __restrict__ sz  = smem + 2 * BN;                    // [BN]

    for (int p = threadIdx.x; p < BN; p += NTHREADS) {
        sxy[p] = make_float2(x[3 * p + 0], x[3 * p + 1]);
        sz[p]  = x[3 * p + 2];
    }
    __syncthreads();

    const int lane = threadIdx.x & 31;
    const int warp = threadIdx.x >> 5;
    const int gw   = blockIdx.x * NW + warp;     // global warp-task id
    if (gw >= NTASKS) return;                    // warp-uniform; after the sync
    const int row0 = gw * R;
    const unsigned FULL = 0xffffffffu;

    // Per-row scalar state — all compile-time indexed (no LMEM).
    float px2[R], py2[R], pz2[R], nsqi[R], cR[R], lv[R];
    int   lj[R];

#pragma unroll
    for (int r = 0; r < R; r++) {
        const float2 pxy = sxy[row0 + r];
        const float  pz  = sz[row0 + r];
        const float sqi = __fadd_rn(__fadd_rn(__fmul_rn(pxy.x, pxy.x),
                                              __fmul_rn(pxy.y, pxy.y)),
                                    __fmul_rn(pz, pz));
        px2[r] = __fadd_rn(pxy.x, pxy.x);   // exact doubling
        py2[r] = __fadd_rn(pxy.y, pxy.y);
        pz2[r] = __fadd_rn(pz, pz);
        nsqi[r] = fneg(sqi);
    }

    // ---- Bootstrap: sort candidates 0..63 per row, seed list with ranks 0..16.
    {
        const float4 xy = *reinterpret_cast<const float4*>(sxy + (lane << 1));
        const float2 zz = *reinterpret_cast<const float2*>(sz + (lane << 1));
        const float nsq0 = fneg(__fadd_rn(__fadd_rn(__fmul_rn(xy.x, xy.x),
                                                    __fmul_rn(xy.y, xy.y)),
                                          __fmul_rn(zz.x, zz.x)));
        const float nsq1 = fneg(__fadd_rn(__fadd_rn(__fmul_rn(xy.z, xy.z),
                                                    __fmul_rn(xy.w, xy.w)),
                                          __fmul_rn(zz.y, zz.y)));
#pragma unroll
        for (int r = 0; r < R; r++) {
            // Exact pv (same formula as slow path -> bit-identical results).
            const float d0 = __fadd_rn(__fadd_rn(__fmul_rn(px2[r], xy.x),
                                                 __fmul_rn(py2[r], xy.y)),
                                       __fmul_rn(pz2[r], zz.x));
            const float d1 = __fadd_rn(__fadd_rn(__fmul_rn(px2[r], xy.z),
                                                 __fmul_rn(py2[r], xy.w)),
                                       __fmul_rn(pz2[r], zz.y));
            float pv0 = __fadd_rn(__fadd_rn(d0, nsqi[r]), nsq0);
            float pv1 = __fadd_rn(__fadd_rn(d1, nsqi[r]), nsq1);
            int   id0 = (lane << 1);
            int   id1 = (lane << 1) + 1;

            // 64-element bitonic sort, ascending lexicographic (pv, id).
#pragma unroll
            for (int k = 2; k <= 64; k <<= 1) {
#pragma unroll
                for (int j = k >> 1; j >= 1; j >>= 1) {
                    const bool asc = (k == 64) || ((lane & (k >> 1)) == 0);
                    if (j >= 2) {
                        const int L = j >> 1;
                        const float opv0 = __shfl_xor_sync(FULL, pv0, L);
                        const float opv1 = __shfl_xor_sync(FULL, pv1, L);
                        const int   oid0 = __shfl_xor_sync(FULL, id0, L);
                        const int   oid1 = __shfl_xor_sync(FULL, id1, L);
                        const bool lower = (lane & L) == 0;
                        const bool keepmin = (asc == lower);
                        const bool l0 = (opv0 < pv0) || (opv0 == pv0 && oid0 < id0);
                        const bool l1 = (opv1 < pv1) || (opv1 == pv1 && oid1 < id1);
                        if (keepmin ? l0 : !l0) { pv0 = opv0; id0 = oid0; }
                        if (keepmin ? l1 : !l1) { pv1 = opv1; id1 = oid1; }
                    } else {
                        const bool less = (pv1 < pv0) || (pv1 == pv0 && id1 < id0);
                        if (asc ? less : !less) {
                            const float tp = pv0; pv0 = pv1; pv1 = tp;
                            const int   ti = id0; id0 = id1; id1 = ti;
                        }
                    }
                }
            }
            // rank v = 2*lane + slot; redistribute so lane l holds rank l (l<=16)
            const float a0 = __shfl_sync(FULL, pv0, lane >> 1);
            const float a1 = __shfl_sync(FULL, pv1, lane >> 1);
            const int   b0 = __shfl_sync(FULL, id0, lane >> 1);
            const int   b1 = __shfl_sync(FULL, id1, lane >> 1);
            lv[r] = (lane <= 16) ? ((lane & 1) ? a1 : a0) : CUDART_INF_F;
            lj[r] = (lane <= 16) ? ((lane & 1) ? b1 : b0) : 0x7fffffff;
            const float nt = __shfl_sync(FULL, lv[r], 16);
            cR[r] = __fsub_rn(__fadd_rn(nsqi[r], fneg(nt)), SLACK);
        }
    }

    // ---- Main loop over candidate groups 1..255 (candidates 64..16383).
    for (int t = 1; t < NITER2; t++) {
        const int j0 = (t << 6) + (lane << 1);       // candidates j0, j0+1
        const float4 xy = *reinterpret_cast<const float4*>(sxy + j0); // LDS.128
        const float2 zz = *reinterpret_cast<const float2*>(sz + j0);  // LDS.64

        // Fast (fma-contracted) sqj per candidate (filter only).
        const float sqA = __fmaf_rn(xy.x, xy.x,
                          __fmaf_rn(xy.y, xy.y, __fmul_rn(zz.x, zz.x)));
        const float sqB = __fmaf_rn(xy.z, xy.z,
                          __fmaf_rn(xy.w, xy.w, __fmul_rn(zz.y, zz.y)));

        // m[r] = 2*dot_r + (-sqi_r - T_r - SLACK), per candidate.
        float mA[R], mB[R];
        float mnA = CUDART_INF_F, mnB = CUDART_INF_F;
#pragma unroll
        for (int r = 0; r < R; r++) {
            mA[r] = __fmaf_rn(pz2[r], zz.x,
                    __fmaf_rn(py2[r], xy.y,
                    __fmaf_rn(px2[r], xy.x, cR[r])));
            mB[r] = __fmaf_rn(pz2[r], zz.y,
                    __fmaf_rn(py2[r], xy.w,
                    __fmaf_rn(px2[r], xy.z, cR[r])));
            mnA = fminf(mnA, mA[r]);
            mnB = fminf(mnB, mB[r]);
        }

        const bool qA = mnA < sqA;
        const bool qB = mnB < sqB;
        if (__any_sync(FULL, qA || qB)) {
            const unsigned gA = __ballot_sync(FULL, qA);
            const unsigned gB = __ballot_sync(FULL, qB);
            const int njbase = t << 6;
            if (gA) PROCESS_CAND(xy.x, xy.y, zz.x, mA, sqA, njbase);
            if (gB) PROCESS_CAND(xy.z, xy.w, zz.y, mB, sqB, njbase + 1);
        }
    }

    // Ranks 1..16 are the output (rank 0 dropped by the reference).
#pragma unroll
    for (int r = 0; r < R; r++) {
        if (lane >= 1 && lane <= 16) {
            const int row = row0 + r;
            out[(size_t)row * KOUT + (lane - 1)] = lv[r];
            out[(size_t)BN * KOUT + (size_t)row * KOUT + (lane - 1)] = (float)lj[r];
        }
    }
}

extern "C" void kernel_launch(void* const* d_in, const int* in_sizes, int n_in,
                              void* d_out, int out_size) {
    const float* x = (const float*)d_in[0];
    float* out = (float*)d_out;
    cudaFuncSetAttribute(knn_kernel, cudaFuncAttributeMaxDynamicSharedMemorySize,
                         SMEM_BYTES);
    knn_kernel<<<NBLOCKS, NTHREADS, SMEM_BYTES>>>(x, out);
}